// round 15
// baseline (speedup 1.0000x reference)
#include <cuda_runtime.h>
#include <cuda_fp16.h>
#include <cstdint>

#define N_CODES 16384
#define N_TOK   8192
#define DIM     512
#define THRESH  900.0f
#define MARGIN  16.0f
#define CAP     1024
#define BM      128
#define BN      256
#define NKC     8                 // kc chunks per n-tile (512/64)
#define NGU     32                // g-iters per unit: 4 n-tiles * 8 kc
#define NUNITS  1024              // 64 token tiles * 16 code slices
#define NCTA    148
#define A_BYTES 131072u
#define STGB    32768u
#define SMEM_DYN (A_BYTES + 2u*STGB)
#define SWZ(o) ((o) ^ (((o)>>3)&0x70))

__device__ __align__(128) __half g_A[(size_t)N_TOK*DIM];
__device__ __align__(128) __half g_B[(size_t)N_CODES*DIM];
__device__ __align__(16) float g_c2[N_CODES];
__device__ __align__(16) float g_x2[N_TOK];
__device__ int g_vmin[N_TOK];
__device__ int g_ccnt[N_TOK];
__device__ int g_cand[(size_t)N_TOK*CAP];

__device__ __forceinline__ uint32_t s2u(const void* p){
    uint32_t a;
    asm("{ .reg .u64 t; cvta.to.shared.u64 t, %1; cvt.u32.u64 %0, t; }" : "=r"(a) : "l"(p));
    return a;
}
__device__ __forceinline__ int fkey(float f){ int i=__float_as_int(f); return i<0 ? (i^0x7FFFFFFF) : i; }
__device__ __forceinline__ float funkey(int i){ return __int_as_float(i<0 ? (i^0x7FFFFFFF) : i); }
#define CPASYNC16(d,s) asm volatile("cp.async.cg.shared.global [%0], [%1], 16;" :: "r"(d),"l"(s) : "memory")
#define LDSM4(r0,r1,r2,r3,a) asm volatile("ldmatrix.sync.aligned.m8n8.x4.shared.b16 {%0,%1,%2,%3}, [%4];" \
    : "=r"(r0),"=r"(r1),"=r"(r2),"=r"(r3) : "r"(a))
// fp16-accumulator HMMA (2 output regs)
#define MMAH(c,a,b0,b1) asm volatile( \
    "mma.sync.aligned.m16n8k16.row.col.f16.f16.f16.f16 {%0,%1},{%2,%3,%4,%5},{%6,%7},{%0,%1};" \
    : "+r"((c)[0]),"+r"((c)[1]) \
    : "r"((a)[0]),"r"((a)[1]),"r"((a)[2]),"r"((a)[3]),"r"(b0),"r"(b1))

// ---- prep: fp32 -> fp16 + norms + init vmin/counters -----------------------
__global__ __launch_bounds__(256) void prep(const float* __restrict__ x,
                                            const float* __restrict__ codes){
    int flat = blockIdx.x*256+threadIdx.x;
    if (flat < N_TOK){ g_ccnt[flat]=0; g_vmin[flat]=0x7F800000; }
    int w=flat>>5, lane=threadIdx.x&31;
    if (w>=N_TOK+N_CODES) return;
    bool isx = w<N_TOK;
    int row = isx ? w : w-N_TOK;
    const float* src = isx ? x+(size_t)row*DIM : codes+(size_t)row*DIM;
    __half* d = isx ? g_A+(size_t)row*DIM : g_B+(size_t)row*DIM;
    float s=0.f;
#pragma unroll
    for (int i=0;i<4;i++){
        float4 v = ((const float4*)src)[lane+32*i];
        int c=(lane+32*i)*4;
        float vv[4]={v.x,v.y,v.z,v.w};
        *(__half2*)(d+c)=__floats2half2_rn(vv[0],vv[1]);
        *(__half2*)(d+c+2)=__floats2half2_rn(vv[2],vv[3]);
#pragma unroll
        for (int u=0;u<4;u++) s=fmaf(vv[u],vv[u],s);
    }
#pragma unroll
    for (int o=16;o>0;o>>=1) s += __shfl_xor_sync(0xffffffffu,s,o);
    if (lane==0){ if (isx) g_x2[row]=s; else g_c2[row]=s; }
}

// ---- B stage load -----------------------------------------------------------
__device__ __forceinline__ void issue_B(uint32_t sd,int tid,int cbase,int g){
    int it=g>>3, kc=g&7;
    uint32_t st = sd + A_BYTES + (uint32_t)(g&1)*STGB;
    const __half* pb = g_B + (size_t)(cbase+it*BN)*DIM + kc*64;
#pragma unroll
    for (int i=0;i<4;i++){
        int id=tid+i*512, r=id>>3, c=id&7;
        CPASYNC16(st + SWZ((uint32_t)(r*128+c*16)), pb + (size_t)r*DIM + c*8);
    }
    asm volatile("cp.async.commit_group;" ::: "memory");
}

__global__ __launch_bounds__(512,1) void nn_hmma(){
    extern __shared__ __align__(1024) char dsm[];
    __shared__ __align__(16) float c2s[BN];
    __shared__ float rv[BM][4];
    __shared__ float pfx[BM];
    const uint32_t sd = s2u(dsm);
    const int tid=threadIdx.x, l=tid&31, wid=tid>>5;
    const int wr=wid>>2, wc=wid&3;
    const int bid=blockIdx.x;

    const int ustart = (bid*NUNITS)/NCTA;
    const int uend   = ((bid+1)*NUNITS)/NCTA;
    int cur_tile = -1;

    for (int u=ustart; u<uend; u++){
        const int tile  = u >> 4;
        const int cbase = (u & 15) * 1024;
        const int row0  = tile * BM;

        uint32_t acc[2][8][2];
#pragma unroll
        for (int a=0;a<2;a++)
#pragma unroll
            for (int b=0;b<8;b++){ acc[a][b][0]=0u; acc[a][b][1]=0u; }

        if (tile != cur_tile){
            cur_tile = tile;
            const __half* pa = g_A + (size_t)row0*DIM;
#pragma unroll
            for (int i=0;i<16;i++){
                int id=tid+i*512;
                int c=id>>10, r=(id>>3)&127, cc=id&7;
                CPASYNC16(sd + (uint32_t)c*16384u + SWZ((uint32_t)(r*128+cc*16)),
                          pa + (size_t)r*DIM + c*64 + cc*8);
            }
        }
        issue_B(sd,tid,cbase,0);
        issue_B(sd,tid,cbase,1);

        for (int g=0; g<NGU; g++){
            const int it=g>>3, kc=g&7;
            if (g>=NGU-2) asm volatile("cp.async.wait_group 0;" ::: "memory");
            else          asm volatile("cp.async.wait_group 1;" ::: "memory");
            __syncthreads();
            if (kc==0 && tid<64)
                *(float4*)(c2s+tid*4) = *(const float4*)(g_c2 + cbase + it*BN + tid*4);

            const uint32_t stA = sd + (uint32_t)kc*16384u;
            const uint32_t stB = sd + A_BYTES + (uint32_t)(g&1)*STGB;
#pragma unroll
            for (int kk=0;kk<4;kk++){
                uint32_t a[2][4];
#pragma unroll
                for (int mt=0;mt<2;mt++){
                    uint32_t row=(uint32_t)(wr*32+mt*16+(l&15));
                    uint32_t col=(uint32_t)(kk*32+((l>>4)<<4));
                    LDSM4(a[mt][0],a[mt][1],a[mt][2],a[mt][3], stA+SWZ(row*128u+col));
                }
#pragma unroll
                for (int nt0=0;nt0<8;nt0+=2){
                    int mi=l>>3;
                    uint32_t brow=(uint32_t)(wc*64+nt0*8+((mi>>1)<<3)+(l&7));
                    uint32_t bcol=(uint32_t)(kk*32+((mi&1)<<4));
                    uint32_t b0,b1,b2,b3;
                    LDSM4(b0,b1,b2,b3, stB+SWZ(brow*128u+bcol));
                    MMAH(acc[0][nt0],a[0],b0,b1);
                    MMAH(acc[1][nt0],a[1],b0,b1);
                    MMAH(acc[0][nt0+1],a[0],b2,b3);
                    MMAH(acc[1][nt0+1],a[1],b2,b3);
                }
            }
            if (kc==NKC-1){
                const int tilen = cbase + it*BN;
                float tmin[2][2];
#pragma unroll
                for (int mt=0;mt<2;mt++){ tmin[mt][0]=3.4e38f; tmin[mt][1]=3.4e38f; }
#pragma unroll
                for (int mt=0;mt<2;mt++)
#pragma unroll
                    for (int nt=0;nt<8;nt++){
                        int nl = wc*64 + nt*8 + (l&3)*2;
                        float c2v0=c2s[nl], c2v1=c2s[nl+1];
                        float2 f0=__half22float2(*(__half2*)&acc[mt][nt][0]);
                        float2 f1=__half22float2(*(__half2*)&acc[mt][nt][1]);
                        float v0=fmaf(-2.f,f0.x,c2v0), v1=fmaf(-2.f,f0.y,c2v1);
                        float v2=fmaf(-2.f,f1.x,c2v0), v3=fmaf(-2.f,f1.y,c2v1);
                        // repack v in place (fp16-rounded; MARGIN covers +-0.5)
                        __half2 h0=__floats2half2_rn(v0,v1);
                        __half2 h1=__floats2half2_rn(v2,v3);
                        acc[mt][nt][0]=*(uint32_t*)&h0;
                        acc[mt][nt][1]=*(uint32_t*)&h1;
                        tmin[mt][0]=fminf(tmin[mt][0],fminf(v0,v1));
                        tmin[mt][1]=fminf(tmin[mt][1],fminf(v2,v3));
                    }
#pragma unroll
                for (int q=1;q<4;q<<=1)
#pragma unroll
                    for (int mt=0;mt<2;mt++){
                        tmin[mt][0]=fminf(tmin[mt][0],__shfl_xor_sync(0xffffffffu,tmin[mt][0],q));
                        tmin[mt][1]=fminf(tmin[mt][1],__shfl_xor_sync(0xffffffffu,tmin[mt][1],q));
                    }
                if ((l&3)==0){
                    int gq=l>>2;
#pragma unroll
                    for (int mt=0;mt<2;mt++){
                        rv[wr*32+mt*16+gq][wc]=tmin[mt][0];
                        rv[wr*32+mt*16+gq+8][wc]=tmin[mt][1];
                    }
                }
                __syncthreads();
                if (tid<BM){
                    float p=fminf(fminf(rv[tid][0],rv[tid][1]),fminf(rv[tid][2],rv[tid][3]));
                    int old = atomicMin(&g_vmin[row0+tid], fkey(p));
                    pfx[tid]=fminf(p, funkey(old));
                }
                __syncthreads();
#pragma unroll
                for (int mt=0;mt<2;mt++){
                    const int m0 = wr*32 + mt*16 + (l>>2);
                    const float th0 = pfx[m0]   + MARGIN;
                    const float th8 = pfx[m0+8] + MARGIN;
                    const int gi0 = row0+m0, gi1 = row0+m0+8;
#pragma unroll
                    for (int nt=0;nt<8;nt++){
                        int nl = tilen + wc*64 + nt*8 + (l&3)*2;
                        float2 w0=__half22float2(*(__half2*)&acc[mt][nt][0]);
                        float2 w1=__half22float2(*(__half2*)&acc[mt][nt][1]);
                        if (w0.x<=th0){ int p=atomicAdd(&g_ccnt[gi0],1); if(p<CAP) g_cand[(size_t)gi0*CAP+p]=nl;   }
                        if (w0.y<=th0){ int p=atomicAdd(&g_ccnt[gi0],1); if(p<CAP) g_cand[(size_t)gi0*CAP+p]=nl+1; }
                        if (w1.x<=th8){ int p=atomicAdd(&g_ccnt[gi1],1); if(p<CAP) g_cand[(size_t)gi1*CAP+p]=nl;   }
                        if (w1.y<=th8){ int p=atomicAdd(&g_ccnt[gi1],1); if(p<CAP) g_cand[(size_t)gi1*CAP+p]=nl+1; }
                        acc[mt][nt][0]=0u; acc[mt][nt][1]=0u;
                    }
                }
            }
            __syncthreads();
            if (g+2<NGU) issue_B(sd,tid,cbase,g+2);
        }
    }
}

// ---- refine: exact fp32 recheck of candidates, warp per token -------------
__global__ __launch_bounds__(256) void refine(const float* __restrict__ x,
                                              const float* __restrict__ codes,
                                              float* __restrict__ out){
    const int t = blockIdx.x*8 + (threadIdx.x>>5);
    const int l = threadIdx.x&31;
    float xr[16];
    {
        const float4* xp = (const float4*)(x + (size_t)t*DIM) + l*4;
#pragma unroll
        for (int u=0;u<4;u++){
            float4 v=xp[u];
            xr[u*4]=v.x; xr[u*4+1]=v.y; xr[u*4+2]=v.z; xr[u*4+3]=v.w;
        }
    }
    const float x2=g_x2[t];
    float bv=3.4e38f; int bi=0x7fffffff;
    int cnt=g_ccnt[t]; if (cnt>CAP) cnt=CAP;
    const int* lst=g_cand+(size_t)t*CAP;
    for (int j=0;j<cnt;j++){
        int ci=lst[j];
        const float4* cp=(const float4*)(codes+(size_t)ci*DIM)+l*4;
        float s=0.f;
#pragma unroll
        for (int u=0;u<4;u++){
            float4 v=cp[u];
            s=fmaf(xr[u*4],v.x,s); s=fmaf(xr[u*4+1],v.y,s);
            s=fmaf(xr[u*4+2],v.z,s); s=fmaf(xr[u*4+3],v.w,s);
        }
#pragma unroll
        for (int o=16;o>0;o>>=1) s += __shfl_xor_sync(0xffffffffu,s,o);
        float dist = x2 + g_c2[ci] - 2.f*s;
        if (dist<bv || (dist==bv && ci<bi)){ bv=dist; bi=ci; }
    }
    if (l==0) out[t] = (bv<=THRESH) ? (float)bi : -1.0f;
}

extern "C" void kernel_launch(void* const* d_in, const int* in_sizes, int n_in,
                              void* d_out, int out_size){
    const float* x=(const float*)d_in[0];
    const float* codes=(const float*)d_in[1];
    float* out=(float*)d_out;
    cudaFuncSetAttribute(nn_hmma, cudaFuncAttributeMaxDynamicSharedMemorySize, SMEM_DYN);
    prep<<<(N_TOK+N_CODES)/8, 256>>>(x, codes);
    nn_hmma<<<NCTA, 512, SMEM_DYN>>>();
    refine<<<N_TOK/8, 256>>>(x, codes, out);
}